// round 16
// baseline (speedup 1.0000x reference)
#include <cuda_runtime.h>
#include <cuda_fp16.h>
#include <math.h>
#include <stdint.h>

#define Bn 1024
#define Tn 64
#define Dn 512
#define Hn 512
#define Cn 96
#define Sn 21
#define DCn (Dn + Cn)   // 608
#define XCn (Dn + Hn)   // 1024
#define ZPH 4           // ph split-K ways

// ---------------- scratch (device globals) ----------------
__device__ __half g_Hp16[(size_t)Bn * Tn * Hn];     // attention score input (fp16 ok)
__device__ __half g_bh16[(size_t)Bn * Tn * Dn];     // ctx accumulation input (fp16 ok)
__device__ float  g_c[Bn * Hn];
__device__ float  g_ph[ZPH * Bn * Hn];              // split-K partials
__device__ float  g_xcat[Bn * XCn];                 // [ctx | h] fp32
__device__ float  g_hs[(size_t)Bn * Sn * Hn];       // fp32 (output path)
__device__ __half g_Wcat16[(size_t)4 * Hn * XCn];   // interleaved rows j=4n+gate (fp16,
                                                    //  same RN rounding the GEMM applied)
__device__ float  g_ohb[Cn * 4 * Hn];               // Wih one-hot col + biases, interleaved

// ---------------- helpers ----------------
__device__ __forceinline__ float tanh_fast(float x) {
    float y;
    asm("tanh.approx.f32 %0, %1;" : "=f"(y) : "f"(x));
    return y;
}
__device__ __forceinline__ float sigmoidf(float x) {
    return 1.0f / (1.0f + expf(-x));
}

// ---------------- prep ----------------
__global__ void conv_f2h(const float* __restrict__ src, __half* __restrict__ dst, int n8) {
    int i = blockIdx.x * blockDim.x + threadIdx.x;
    if (i >= n8) return;
    float4 a = reinterpret_cast<const float4*>(src)[2 * i];
    float4 b = reinterpret_cast<const float4*>(src)[2 * i + 1];
    __half2* d = reinterpret_cast<__half2*>(dst) + 4 * (size_t)i;
    d[0] = __floats2half2_rn(a.x, a.y);
    d[1] = __floats2half2_rn(a.z, a.w);
    d[2] = __floats2half2_rn(b.x, b.y);
    d[3] = __floats2half2_rn(b.z, b.w);
}
__global__ void build_wcat_kernel(const float* __restrict__ Wih,
                                  const float* __restrict__ Whh) {
    int idx = blockIdx.x * blockDim.x + threadIdx.x;
    if (idx >= 4 * Hn * XCn) return;
    int j = idx >> 10;
    int k = idx & 1023;
    int gate = j & 3, n = j >> 2;
    int r = gate * Hn + n;
    float v = (k < Dn) ? Wih[(size_t)r * DCn + k] : Whh[(size_t)r * Hn + (k - Dn)];
    g_Wcat16[idx] = __float2half_rn(v);   // RN — identical to the GEMM's smem-store rounding
}
__global__ void build_ohb_kernel(const float* __restrict__ Wih,
                                 const float* __restrict__ bih,
                                 const float* __restrict__ bhh) {
    int idx = blockIdx.x * blockDim.x + threadIdx.x;
    if (idx >= Cn * 4 * Hn) return;
    int c = idx / (4 * Hn);
    int j = idx % (4 * Hn);
    int gate = j & 3, n = j >> 2;
    int r = gate * Hn + n;
    g_ohb[idx] = Wih[(size_t)r * DCn + Dn + c] + bih[r] + bhh[r];
}
__global__ void init_state_kernel() {
    int i = blockIdx.x * blockDim.x + threadIdx.x;
    if (i < Bn * Hn) {
        g_c[i] = 0.0f;
        g_xcat[(i / Hn) * XCn + Dn + (i % Hn)] = 0.0f;
    }
}

// ---------------- fp16-operand tensor-core GEMM (128x64 tile, 256 thr) ----------
// MODE 1: fp32 C + bias, gridDim.z split-K (bias z==0 only).
// MODE 2: fp32 C + bias, ragged-N guard (Np) on B loads and C stores.
// MODE 4: fp16 C store.
template <int MODE>
__global__ __launch_bounds__(256)
void hgemm(const float* __restrict__ A, int lda,
           const float* __restrict__ B, int ldb,
           const float* __restrict__ bias,
           void* __restrict__ Cv, int ldc,
           int M, int Np, int K)
{
    __shared__ __align__(16) unsigned char smraw[(128 * 40 + 64 * 40) * 2];
    __half* As = reinterpret_cast<__half*>(smraw);                  // [128][40]
    __half* Bs = reinterpret_cast<__half*>(smraw + 128 * 40 * 2);   // [64][40]

    const int tid = threadIdx.x;
    const int warp = tid >> 5, lane = tid & 31;
    const int g = lane >> 2, tig = lane & 3;
    const int wm = warp >> 1, wn = warp & 1;
    const int m0 = blockIdx.y * 128, n0 = blockIdx.x * 64;

    if (MODE == 1) {
        int z = blockIdx.z;
        A += (size_t)z * K;
        B += (size_t)z * K;
        Cv = (void*)((float*)Cv + (size_t)z * M * ldc);
        if (z != 0) bias = nullptr;
    }

    const float* Aptr = A + (size_t)m0 * lda;
    const float* Bptr = B + (size_t)n0 * ldb;

    float4 pa[4], pb[2];
    float acc[2][4][4];
#pragma unroll
    for (int i = 0; i < 2; i++)
#pragma unroll
        for (int j = 0; j < 4; j++)
#pragma unroll
            for (int l = 0; l < 4; l++) acc[i][j][l] = 0.0f;

#pragma unroll
    for (int v = 0; v < 4; v++) {
        int f = tid + v * 256;
        pa[v] = *reinterpret_cast<const float4*>(Aptr + (size_t)(f >> 3) * lda + ((f & 7) << 2));
    }
#pragma unroll
    for (int v = 0; v < 2; v++) {
        int f = tid + v * 256;
        if (MODE == 2 && n0 + (f >> 3) >= Np) pb[v] = make_float4(0.f, 0.f, 0.f, 0.f);
        else pb[v] = *reinterpret_cast<const float4*>(Bptr + (size_t)(f >> 3) * ldb + ((f & 7) << 2));
    }

    for (int k0 = 0; k0 < K; k0 += 32) {
#pragma unroll
        for (int v = 0; v < 4; v++) {
            int f = tid + v * 256; int r = f >> 3, c = (f & 7) << 2;
            *reinterpret_cast<__half2*>(&As[r * 40 + c])     = __floats2half2_rn(pa[v].x, pa[v].y);
            *reinterpret_cast<__half2*>(&As[r * 40 + c + 2]) = __floats2half2_rn(pa[v].z, pa[v].w);
        }
#pragma unroll
        for (int v = 0; v < 2; v++) {
            int f = tid + v * 256; int r = f >> 3, c = (f & 7) << 2;
            *reinterpret_cast<__half2*>(&Bs[r * 40 + c])     = __floats2half2_rn(pb[v].x, pb[v].y);
            *reinterpret_cast<__half2*>(&Bs[r * 40 + c + 2]) = __floats2half2_rn(pb[v].z, pb[v].w);
        }
        __syncthreads();

        if (k0 + 32 < K) {
            const float* An  = Aptr + k0 + 32;
            const float* Bnp = Bptr + k0 + 32;
#pragma unroll
            for (int v = 0; v < 4; v++) {
                int f = tid + v * 256;
                pa[v] = *reinterpret_cast<const float4*>(An + (size_t)(f >> 3) * lda + ((f & 7) << 2));
            }
#pragma unroll
            for (int v = 0; v < 2; v++) {
                int f = tid + v * 256;
                if (MODE == 2 && n0 + (f >> 3) >= Np) pb[v] = make_float4(0.f, 0.f, 0.f, 0.f);
                else pb[v] = *reinterpret_cast<const float4*>(Bnp + (size_t)(f >> 3) * ldb + ((f & 7) << 2));
            }
        }

#pragma unroll
        for (int ks = 0; ks < 2; ks++) {
            const int kk = ks * 16;
            uint32_t af[2][4], bf[4][2];
#pragma unroll
            for (int mt = 0; mt < 2; mt++) {
                int mb = wm * 32 + mt * 16;
                af[mt][0] = *reinterpret_cast<const uint32_t*>(&As[(mb + g) * 40 + kk + 2 * tig]);
                af[mt][1] = *reinterpret_cast<const uint32_t*>(&As[(mb + g + 8) * 40 + kk + 2 * tig]);
                af[mt][2] = *reinterpret_cast<const uint32_t*>(&As[(mb + g) * 40 + kk + 2 * tig + 8]);
                af[mt][3] = *reinterpret_cast<const uint32_t*>(&As[(mb + g + 8) * 40 + kk + 2 * tig + 8]);
            }
#pragma unroll
            for (int nt = 0; nt < 4; nt++) {
                int nb = wn * 32 + nt * 8 + g;
                bf[nt][0] = *reinterpret_cast<const uint32_t*>(&Bs[nb * 40 + kk + 2 * tig]);
                bf[nt][1] = *reinterpret_cast<const uint32_t*>(&Bs[nb * 40 + kk + 2 * tig + 8]);
            }
#pragma unroll
            for (int mt = 0; mt < 2; mt++)
#pragma unroll
                for (int nt = 0; nt < 4; nt++)
                    asm volatile(
                        "mma.sync.aligned.m16n8k16.row.col.f32.f16.f16.f32 "
                        "{%0,%1,%2,%3}, {%4,%5,%6,%7}, {%8,%9}, {%0,%1,%2,%3};"
                        : "+f"(acc[mt][nt][0]), "+f"(acc[mt][nt][1]),
                          "+f"(acc[mt][nt][2]), "+f"(acc[mt][nt][3])
                        : "r"(af[mt][0]), "r"(af[mt][1]), "r"(af[mt][2]), "r"(af[mt][3]),
                          "r"(bf[nt][0]), "r"(bf[nt][1]));
        }
        __syncthreads();
    }

#pragma unroll
    for (int mt = 0; mt < 2; mt++) {
        int row = m0 + wm * 32 + mt * 16 + g;
#pragma unroll
        for (int nt = 0; nt < 4; nt++) {
            int col = n0 + wn * 32 + nt * 8 + 2 * tig;
            if (MODE == 2 && col >= Np) continue;
            if (MODE == 4) {
                __half* C = (__half*)Cv;
                *reinterpret_cast<__half2*>(&C[(size_t)row * ldc + col]) =
                    __floats2half2_rn(acc[mt][nt][0], acc[mt][nt][1]);
                *reinterpret_cast<__half2*>(&C[(size_t)(row + 8) * ldc + col]) =
                    __floats2half2_rn(acc[mt][nt][2], acc[mt][nt][3]);
            } else {
                float* C = (float*)Cv;
                float b0 = bias ? bias[col] : 0.f;
                float b1 = bias ? bias[col + 1] : 0.f;
                *reinterpret_cast<float2*>(&C[(size_t)row * ldc + col]) =
                    make_float2(acc[mt][nt][0] + b0, acc[mt][nt][1] + b1);
                *reinterpret_cast<float2*>(&C[(size_t)(row + 8) * ldc + col]) =
                    make_float2(acc[mt][nt][2] + b0, acc[mt][nt][3] + b1);
            }
        }
    }
}

// ---------------- gates GEMM 128x128x32, 512 threads, fused LSTM ----------------
// A = g_xcat fp32 (converted at smem store, unchanged). B = g_Wcat16 fp16 (pre-rounded).
// grid (16, 8) = 128 CTAs (one full wave). Warps 4m x 4n, warp tile 32x32.
__global__ __launch_bounds__(512)
void gates_kernel(const int* __restrict__ text, int s)
{
    __shared__ __align__(16) unsigned char smraw[36864];
    __half* As = reinterpret_cast<__half*>(smraw);                  // [128][40]
    __half* Bs = reinterpret_cast<__half*>(smraw + 128 * 40 * 2);   // [128][40]

    const int tid = threadIdx.x;
    const int warp = tid >> 5, lane = tid & 31;
    const int g = lane >> 2, tig = lane & 3;
    const int wm = warp >> 2, wn = warp & 3;
    const int m0 = blockIdx.y * 128, n0 = blockIdx.x * 128;

    const float*  Aptr = g_xcat + (size_t)m0 * XCn;
    const __half* Bptr = g_Wcat16 + (size_t)n0 * XCn;

    float4 pa[2];
    uint4 pb16;
    float acc[2][4][4];
#pragma unroll
    for (int i = 0; i < 2; i++)
#pragma unroll
        for (int j = 0; j < 4; j++)
#pragma unroll
            for (int l = 0; l < 4; l++) acc[i][j][l] = 0.0f;

#pragma unroll
    for (int v = 0; v < 2; v++) {
        int f = tid + v * 512;
        pa[v] = *reinterpret_cast<const float4*>(Aptr + (size_t)(f >> 3) * XCn + ((f & 7) << 2));
    }
    {
        int f = tid;   // 0..511: row f>>2 (0..127), col (f&3)*8
        pb16 = *reinterpret_cast<const uint4*>(Bptr + (size_t)(f >> 2) * XCn + ((f & 3) << 3));
    }

    for (int k0 = 0; k0 < XCn; k0 += 32) {
#pragma unroll
        for (int v = 0; v < 2; v++) {
            int f = tid + v * 512; int r = f >> 3, c = (f & 7) << 2;
            *reinterpret_cast<__half2*>(&As[r * 40 + c])     = __floats2half2_rn(pa[v].x, pa[v].y);
            *reinterpret_cast<__half2*>(&As[r * 40 + c + 2]) = __floats2half2_rn(pa[v].z, pa[v].w);
        }
        {
            int f = tid; int r = f >> 2, c = (f & 3) << 3;
            *reinterpret_cast<uint4*>(&Bs[r * 40 + c]) = pb16;
        }
        __syncthreads();

        if (k0 + 32 < XCn) {
            const float*  An  = Aptr + k0 + 32;
            const __half* Bnp = Bptr + k0 + 32;
#pragma unroll
            for (int v = 0; v < 2; v++) {
                int f = tid + v * 512;
                pa[v] = *reinterpret_cast<const float4*>(An + (size_t)(f >> 3) * XCn + ((f & 7) << 2));
            }
            {
                int f = tid;
                pb16 = *reinterpret_cast<const uint4*>(Bnp + (size_t)(f >> 2) * XCn + ((f & 3) << 3));
            }
        }

#pragma unroll
        for (int ks = 0; ks < 2; ks++) {
            const int kk = ks * 16;
            uint32_t af[2][4], bf[4][2];
#pragma unroll
            for (int mt = 0; mt < 2; mt++) {
                int mb = wm * 32 + mt * 16;
                af[mt][0] = *reinterpret_cast<const uint32_t*>(&As[(mb + g) * 40 + kk + 2 * tig]);
                af[mt][1] = *reinterpret_cast<const uint32_t*>(&As[(mb + g + 8) * 40 + kk + 2 * tig]);
                af[mt][2] = *reinterpret_cast<const uint32_t*>(&As[(mb + g) * 40 + kk + 2 * tig + 8]);
                af[mt][3] = *reinterpret_cast<const uint32_t*>(&As[(mb + g + 8) * 40 + kk + 2 * tig + 8]);
            }
#pragma unroll
            for (int nt = 0; nt < 4; nt++) {
                int nb = wn * 32 + nt * 8 + g;
                bf[nt][0] = *reinterpret_cast<const uint32_t*>(&Bs[nb * 40 + kk + 2 * tig]);
                bf[nt][1] = *reinterpret_cast<const uint32_t*>(&Bs[nb * 40 + kk + 2 * tig + 8]);
            }
#pragma unroll
            for (int mt = 0; mt < 2; mt++)
#pragma unroll
                for (int nt = 0; nt < 4; nt++)
                    asm volatile(
                        "mma.sync.aligned.m16n8k16.row.col.f32.f16.f16.f32 "
                        "{%0,%1,%2,%3}, {%4,%5,%6,%7}, {%8,%9}, {%0,%1,%2,%3};"
                        : "+f"(acc[mt][nt][0]), "+f"(acc[mt][nt][1]),
                          "+f"(acc[mt][nt][2]), "+f"(acc[mt][nt][3])
                        : "r"(af[mt][0]), "r"(af[mt][1]), "r"(af[mt][2]), "r"(af[mt][3]),
                          "r"(bf[nt][0]), "r"(bf[nt][1]));
        }
        __syncthreads();
    }

    // fused LSTM epilogue in two 64-col passes through reused smem buffer
    float* gbuf = reinterpret_cast<float*>(smraw);   // [128][72]
#pragma unroll
    for (int p = 0; p < 2; p++) {
        if (p) __syncthreads();            // protect gbuf reuse
        if ((wn >> 1) == p) {
#pragma unroll
            for (int mt = 0; mt < 2; mt++) {
                int row = wm * 32 + mt * 16 + g;
#pragma unroll
                for (int nt = 0; nt < 4; nt++) {
                    int col = (wn & 1) * 32 + nt * 8 + 2 * tig;
                    gbuf[row * 72 + col]           = acc[mt][nt][0];
                    gbuf[row * 72 + col + 1]       = acc[mt][nt][1];
                    gbuf[(row + 8) * 72 + col]     = acc[mt][nt][2];
                    gbuf[(row + 8) * 72 + col + 1] = acc[mt][nt][3];
                }
            }
        }
        __syncthreads();
#pragma unroll
        for (int it = 0; it < 4; it++) {
            int idx = it * 512 + tid;          // 0..2047
            int bl = idx >> 4, nl = idx & 15;
            int b = m0 + bl;
            int ng = (n0 >> 2) + p * 16 + nl;  // output unit index
            float4 gv = *reinterpret_cast<const float4*>(&gbuf[bl * 72 + 4 * nl]);
            int tok = text[b * Sn + s];
            float4 ov = *reinterpret_cast<const float4*>(&g_ohb[(size_t)tok * 4 * Hn + 4 * ng]);
            float ig = gv.x + ov.x;
            float fg = gv.y + ov.y;
            float gg = gv.z + ov.z;
            float og = gv.w + ov.w;
            float c_old = g_c[b * Hn + ng];
            float cn = sigmoidf(fg) * c_old + sigmoidf(ig) * tanhf(gg);
            float hn = sigmoidf(og) * tanhf(cn);
            g_c[b * Hn + ng] = cn;
            g_xcat[b * XCn + Dn + ng] = hn;
            g_hs[((size_t)b * Sn + s) * Hn + ng] = hn;
        }
    }
}

// ---------------- fused attention (fp16 Hp / fp16 batch_H, fp32 elsewhere) -------
__global__ __launch_bounds__(256)
void attn_kernel(const float* __restrict__ Ws)
{
    const int b = blockIdx.x;
    __shared__ float2 ph2_s[256];
    __shared__ float2 ws2_s[256];
    __shared__ float e_s[Tn];
    __shared__ float alpha_s[Tn];

    const int tid = threadIdx.x;
    {
        float2 a = reinterpret_cast<const float2*>(g_ph + b * Hn)[tid];
#pragma unroll
        for (int z = 1; z < ZPH; z++) {
            float2 v = reinterpret_cast<const float2*>(g_ph + (size_t)z * Bn * Hn + b * Hn)[tid];
            a.x += v.x; a.y += v.y;
        }
        ph2_s[tid] = a;
        ws2_s[tid] = reinterpret_cast<const float2*>(Ws)[tid];
    }
    __syncthreads();

    const int warp = tid >> 5, lane = tid & 31;
    const __half2* hp2 = reinterpret_cast<const __half2*>(g_Hp16 + (size_t)b * Tn * Hn);

    // two score rows per warp per round (more MLP)
#pragma unroll
    for (int rr = 0; rr < 4; rr++) {
        int t0 = rr * 16 + warp * 2;
        const __half2* hA = hp2 + (size_t)t0 * 256;
        const __half2* hB = hA + 256;
        float a0 = 0.0f, a1 = 0.0f;
#pragma unroll
        for (int j = 0; j < 8; j++) {
            int h2 = lane + j * 32;
            float2 p = ph2_s[h2], w = ws2_s[h2];
            float2 vA = __half22float2(hA[h2]);
            float2 vB = __half22float2(hB[h2]);
            a0 = fmaf(tanh_fast(vA.x + p.x), w.x, a0);
            a0 = fmaf(tanh_fast(vA.y + p.y), w.y, a0);
            a1 = fmaf(tanh_fast(vB.x + p.x), w.x, a1);
            a1 = fmaf(tanh_fast(vB.y + p.y), w.y, a1);
        }
#pragma unroll
        for (int o = 16; o > 0; o >>= 1) {
            a0 += __shfl_xor_sync(0xffffffffu, a0, o);
            a1 += __shfl_xor_sync(0xffffffffu, a1, o);
        }
        if (lane == 0) { e_s[t0] = a0; e_s[t0 + 1] = a1; }
    }
    __syncthreads();

    if (warp == 0) {
        float e0 = e_s[lane], e1 = e_s[lane + 32];
        float m = fmaxf(e0, e1);
#pragma unroll
        for (int o = 16; o > 0; o >>= 1)
            m = fmaxf(m, __shfl_xor_sync(0xffffffffu, m, o));
        float x0 = expf(e0 - m), x1 = expf(e1 - m);
        float sum = x0 + x1;
#pragma unroll
        for (int o = 16; o > 0; o >>= 1)
            sum += __shfl_xor_sync(0xffffffffu, sum, o);
        float inv = 1.0f / sum;
        alpha_s[lane] = x0 * inv;
        alpha_s[lane + 32] = x1 * inv;
    }
    __syncthreads();

    const __half2* bh2 = reinterpret_cast<const __half2*>(g_bh16 + (size_t)b * Tn * Dn);
    float ax = 0.0f, ay = 0.0f;
#pragma unroll 16
    for (int t = 0; t < Tn; t++) {
        float al = alpha_s[t];
        float2 v = __half22float2(bh2[t * 256 + tid]);
        ax = fmaf(al, v.x, ax);
        ay = fmaf(al, v.y, ay);
    }
    reinterpret_cast<float2*>(g_xcat + (size_t)b * XCn)[tid] = make_float2(ax, ay);
}

// ---------------- launch ----------------
extern "C" void kernel_launch(void* const* d_in, const int* in_sizes, int n_in,
                              void* d_out, int out_size)
{
    const float* batch_H = (const float*)d_in[0];
    const int*   text    = (const int*)  d_in[1];
    const float* Wi      = (const float*)d_in[2];
    const float* Wh      = (const float*)d_in[3];
    const float* bh      = (const float*)d_in[4];
    const float* Ws      = (const float*)d_in[5];
    const float* Wih     = (const float*)d_in[6];
    const float* Whh     = (const float*)d_in[7];
    const float* bih     = (const float*)d_in[8];
    const float* bhh     = (const float*)d_in[9];
    const float* Wg      = (const float*)d_in[10];
    const float* bg      = (const float*)d_in[11];
    float* out = (float*)d_out;

    __half *Hp16, *bh16;
    float *ph, *xcat, *hs;
    cudaGetSymbolAddress((void**)&Hp16, g_Hp16);
    cudaGetSymbolAddress((void**)&bh16, g_bh16);
    cudaGetSymbolAddress((void**)&ph,   g_ph);
    cudaGetSymbolAddress((void**)&xcat, g_xcat);
    cudaGetSymbolAddress((void**)&hs,   g_hs);

    // prep
    conv_f2h<<<(Bn * Tn * Dn / 8 + 255) / 256, 256>>>(batch_H, bh16, Bn * Tn * Dn / 8);
    build_wcat_kernel<<<(4 * Hn * XCn + 255) / 256, 256>>>(Wih, Whh);
    build_ohb_kernel<<<(Cn * 4 * Hn + 255) / 256, 256>>>(Wih, bih, bhh);
    init_state_kernel<<<(Bn * Hn + 255) / 256, 256>>>();

    // Hp16 = batch_H @ Wi^T (fp16 mma, fp16 store)
    hgemm<4><<<dim3(Hn / 64, (Bn * Tn) / 128), 256>>>(
        batch_H, Dn, Wi, Dn, nullptr, Hp16, Hn, Bn * Tn, Hn, Dn);

    for (int s = 0; s < Sn; s++) {
        // ph partials: z in {0..3}, K=128 each (bias on z=0)
        hgemm<1><<<dim3(Hn / 64, Bn / 128, ZPH), 256>>>(
            xcat + Dn, XCn, Wh, Hn, bh, ph, Hn, Bn, Hn, Hn / ZPH);

        attn_kernel<<<Bn, 256>>>(Ws);

        // gates 128x128 tile, one wave, fused LSTM (B pre-converted fp16)
        gates_kernel<<<dim3(4 * Hn / 128, Bn / 128), 512>>>(text, s);
    }

    // probs = hs @ Wg^T + bg  (fp16 mma, fp32 out, ragged N=96)
    hgemm<2><<<dim3(2, (Bn * Sn) / 128), 256>>>(
        hs, Hn, Wg, Hn, bg, out, Cn, Bn * Sn, Cn, Hn);
}

// round 17
// speedup vs baseline: 1.0592x; 1.0592x over previous
#include <cuda_runtime.h>
#include <cuda_fp16.h>
#include <math.h>
#include <stdint.h>

#define Bn 1024
#define Tn 64
#define Dn 512
#define Hn 512
#define Cn 96
#define Sn 21
#define DCn (Dn + Cn)   // 608
#define XCn (Dn + Hn)   // 1024
#define ZPH 4           // ph split-K ways

// ---------------- scratch (device globals) ----------------
__device__ __half g_Hp16[(size_t)Bn * Tn * Hn];     // attention score input (fp16 ok)
__device__ __half g_bh16[(size_t)Bn * Tn * Dn];     // ctx accumulation input (fp16 ok)
__device__ float  g_c[Bn * Hn];
__device__ float  g_ph[ZPH * Bn * Hn];              // split-K partials
__device__ float  g_xcat[Bn * XCn];                 // [ctx | h] fp32
__device__ float  g_hs[(size_t)Bn * Sn * Hn];       // fp32 (output path)
__device__ float  g_Wcat[(size_t)4 * Hn * XCn];     // interleaved rows j=4n+gate (fp32)
__device__ float  g_ohb[Cn * 4 * Hn];               // Wih one-hot col + biases, interleaved

// ---------------- helpers ----------------
__device__ __forceinline__ float tanh_fast(float x) {
    float y;
    asm("tanh.approx.f32 %0, %1;" : "=f"(y) : "f"(x));
    return y;
}
__device__ __forceinline__ float sigmoidf(float x) {
    return 1.0f / (1.0f + expf(-x));
}

// ---------------- prep ----------------
__global__ void conv_f2h(const float* __restrict__ src, __half* __restrict__ dst, int n8) {
    int i = blockIdx.x * blockDim.x + threadIdx.x;
    if (i >= n8) return;
    float4 a = reinterpret_cast<const float4*>(src)[2 * i];
    float4 b = reinterpret_cast<const float4*>(src)[2 * i + 1];
    __half2* d = reinterpret_cast<__half2*>(dst) + 4 * (size_t)i;
    d[0] = __floats2half2_rn(a.x, a.y);
    d[1] = __floats2half2_rn(a.z, a.w);
    d[2] = __floats2half2_rn(b.x, b.y);
    d[3] = __floats2half2_rn(b.z, b.w);
}
__global__ void build_wcat_kernel(const float* __restrict__ Wih,
                                  const float* __restrict__ Whh) {
    int idx = blockIdx.x * blockDim.x + threadIdx.x;
    if (idx >= 4 * Hn * XCn) return;
    int j = idx >> 10;
    int k = idx & 1023;
    int gate = j & 3, n = j >> 2;
    int r = gate * Hn + n;
    float v = (k < Dn) ? Wih[(size_t)r * DCn + k] : Whh[(size_t)r * Hn + (k - Dn)];
    g_Wcat[idx] = v;
}
__global__ void build_ohb_kernel(const float* __restrict__ Wih,
                                 const float* __restrict__ bih,
                                 const float* __restrict__ bhh) {
    int idx = blockIdx.x * blockDim.x + threadIdx.x;
    if (idx >= Cn * 4 * Hn) return;
    int c = idx / (4 * Hn);
    int j = idx % (4 * Hn);
    int gate = j & 3, n = j >> 2;
    int r = gate * Hn + n;
    g_ohb[idx] = Wih[(size_t)r * DCn + Dn + c] + bih[r] + bhh[r];
}
__global__ void init_state_kernel() {
    int i = blockIdx.x * blockDim.x + threadIdx.x;
    if (i < Bn * Hn) {
        g_c[i] = 0.0f;
        g_xcat[(i / Hn) * XCn + Dn + (i % Hn)] = 0.0f;
    }
}

// ---------------- fp16-operand tensor-core GEMM (128x64 tile, 256 thr) ----------
// MODE 1: fp32 C + bias, gridDim.z split-K (bias z==0 only).
// MODE 2: fp32 C + bias, ragged-N guard (Np) on B loads and C stores.
// MODE 4: fp16 C store.
template <int MODE>
__global__ __launch_bounds__(256)
void hgemm(const float* __restrict__ A, int lda,
           const float* __restrict__ B, int ldb,
           const float* __restrict__ bias,
           void* __restrict__ Cv, int ldc,
           int M, int Np, int K)
{
    __shared__ __align__(16) unsigned char smraw[(128 * 40 + 64 * 40) * 2];
    __half* As = reinterpret_cast<__half*>(smraw);                  // [128][40]
    __half* Bs = reinterpret_cast<__half*>(smraw + 128 * 40 * 2);   // [64][40]

    const int tid = threadIdx.x;
    const int warp = tid >> 5, lane = tid & 31;
    const int g = lane >> 2, tig = lane & 3;
    const int wm = warp >> 1, wn = warp & 1;
    const int m0 = blockIdx.y * 128, n0 = blockIdx.x * 64;

    if (MODE == 1) {
        int z = blockIdx.z;
        A += (size_t)z * K;
        B += (size_t)z * K;
        Cv = (void*)((float*)Cv + (size_t)z * M * ldc);
        if (z != 0) bias = nullptr;
    }

    const float* Aptr = A + (size_t)m0 * lda;
    const float* Bptr = B + (size_t)n0 * ldb;

    float4 pa[4], pb[2];
    float acc[2][4][4];
#pragma unroll
    for (int i = 0; i < 2; i++)
#pragma unroll
        for (int j = 0; j < 4; j++)
#pragma unroll
            for (int l = 0; l < 4; l++) acc[i][j][l] = 0.0f;

#pragma unroll
    for (int v = 0; v < 4; v++) {
        int f = tid + v * 256;
        pa[v] = *reinterpret_cast<const float4*>(Aptr + (size_t)(f >> 3) * lda + ((f & 7) << 2));
    }
#pragma unroll
    for (int v = 0; v < 2; v++) {
        int f = tid + v * 256;
        if (MODE == 2 && n0 + (f >> 3) >= Np) pb[v] = make_float4(0.f, 0.f, 0.f, 0.f);
        else pb[v] = *reinterpret_cast<const float4*>(Bptr + (size_t)(f >> 3) * ldb + ((f & 7) << 2));
    }

    for (int k0 = 0; k0 < K; k0 += 32) {
#pragma unroll
        for (int v = 0; v < 4; v++) {
            int f = tid + v * 256; int r = f >> 3, c = (f & 7) << 2;
            *reinterpret_cast<__half2*>(&As[r * 40 + c])     = __floats2half2_rn(pa[v].x, pa[v].y);
            *reinterpret_cast<__half2*>(&As[r * 40 + c + 2]) = __floats2half2_rn(pa[v].z, pa[v].w);
        }
#pragma unroll
        for (int v = 0; v < 2; v++) {
            int f = tid + v * 256; int r = f >> 3, c = (f & 7) << 2;
            *reinterpret_cast<__half2*>(&Bs[r * 40 + c])     = __floats2half2_rn(pb[v].x, pb[v].y);
            *reinterpret_cast<__half2*>(&Bs[r * 40 + c + 2]) = __floats2half2_rn(pb[v].z, pb[v].w);
        }
        __syncthreads();

        if (k0 + 32 < K) {
            const float* An  = Aptr + k0 + 32;
            const float* Bnp = Bptr + k0 + 32;
#pragma unroll
            for (int v = 0; v < 4; v++) {
                int f = tid + v * 256;
                pa[v] = *reinterpret_cast<const float4*>(An + (size_t)(f >> 3) * lda + ((f & 7) << 2));
            }
#pragma unroll
            for (int v = 0; v < 2; v++) {
                int f = tid + v * 256;
                if (MODE == 2 && n0 + (f >> 3) >= Np) pb[v] = make_float4(0.f, 0.f, 0.f, 0.f);
                else pb[v] = *reinterpret_cast<const float4*>(Bnp + (size_t)(f >> 3) * ldb + ((f & 7) << 2));
            }
        }

#pragma unroll
        for (int ks = 0; ks < 2; ks++) {
            const int kk = ks * 16;
            uint32_t af[2][4], bf[4][2];
#pragma unroll
            for (int mt = 0; mt < 2; mt++) {
                int mb = wm * 32 + mt * 16;
                af[mt][0] = *reinterpret_cast<const uint32_t*>(&As[(mb + g) * 40 + kk + 2 * tig]);
                af[mt][1] = *reinterpret_cast<const uint32_t*>(&As[(mb + g + 8) * 40 + kk + 2 * tig]);
                af[mt][2] = *reinterpret_cast<const uint32_t*>(&As[(mb + g) * 40 + kk + 2 * tig + 8]);
                af[mt][3] = *reinterpret_cast<const uint32_t*>(&As[(mb + g + 8) * 40 + kk + 2 * tig + 8]);
            }
#pragma unroll
            for (int nt = 0; nt < 4; nt++) {
                int nb = wn * 32 + nt * 8 + g;
                bf[nt][0] = *reinterpret_cast<const uint32_t*>(&Bs[nb * 40 + kk + 2 * tig]);
                bf[nt][1] = *reinterpret_cast<const uint32_t*>(&Bs[nb * 40 + kk + 2 * tig + 8]);
            }
#pragma unroll
            for (int mt = 0; mt < 2; mt++)
#pragma unroll
                for (int nt = 0; nt < 4; nt++)
                    asm volatile(
                        "mma.sync.aligned.m16n8k16.row.col.f32.f16.f16.f32 "
                        "{%0,%1,%2,%3}, {%4,%5,%6,%7}, {%8,%9}, {%0,%1,%2,%3};"
                        : "+f"(acc[mt][nt][0]), "+f"(acc[mt][nt][1]),
                          "+f"(acc[mt][nt][2]), "+f"(acc[mt][nt][3])
                        : "r"(af[mt][0]), "r"(af[mt][1]), "r"(af[mt][2]), "r"(af[mt][3]),
                          "r"(bf[nt][0]), "r"(bf[nt][1]));
        }
        __syncthreads();
    }

#pragma unroll
    for (int mt = 0; mt < 2; mt++) {
        int row = m0 + wm * 32 + mt * 16 + g;
#pragma unroll
        for (int nt = 0; nt < 4; nt++) {
            int col = n0 + wn * 32 + nt * 8 + 2 * tig;
            if (MODE == 2 && col >= Np) continue;
            if (MODE == 4) {
                __half* C = (__half*)Cv;
                *reinterpret_cast<__half2*>(&C[(size_t)row * ldc + col]) =
                    __floats2half2_rn(acc[mt][nt][0], acc[mt][nt][1]);
                *reinterpret_cast<__half2*>(&C[(size_t)(row + 8) * ldc + col]) =
                    __floats2half2_rn(acc[mt][nt][2], acc[mt][nt][3]);
            } else {
                float* C = (float*)Cv;
                float b0 = bias ? bias[col] : 0.f;
                float b1 = bias ? bias[col + 1] : 0.f;
                *reinterpret_cast<float2*>(&C[(size_t)row * ldc + col]) =
                    make_float2(acc[mt][nt][0] + b0, acc[mt][nt][1] + b1);
                *reinterpret_cast<float2*>(&C[(size_t)(row + 8) * ldc + col]) =
                    make_float2(acc[mt][nt][2] + b0, acc[mt][nt][3] + b1);
            }
        }
    }
}

// ---------------- gates GEMM 128x128x32, 512 threads, fused LSTM ----------------
// grid (16, 8) = 128 CTAs (one full wave). Warps 4m x 4n, warp tile 32x32.
__global__ __launch_bounds__(512)
void gates_kernel(const int* __restrict__ text, int s)
{
    __shared__ __align__(16) unsigned char smraw[36864];
    __half* As = reinterpret_cast<__half*>(smraw);                  // [128][40]
    __half* Bs = reinterpret_cast<__half*>(smraw + 128 * 40 * 2);   // [128][40]

    const int tid = threadIdx.x;
    const int warp = tid >> 5, lane = tid & 31;
    const int g = lane >> 2, tig = lane & 3;
    const int wm = warp >> 2, wn = warp & 3;
    const int m0 = blockIdx.y * 128, n0 = blockIdx.x * 128;

    const float* Aptr = g_xcat + (size_t)m0 * XCn;
    const float* Bptr = g_Wcat + (size_t)n0 * XCn;

    float4 pa[2], pb[2];
    float acc[2][4][4];
#pragma unroll
    for (int i = 0; i < 2; i++)
#pragma unroll
        for (int j = 0; j < 4; j++)
#pragma unroll
            for (int l = 0; l < 4; l++) acc[i][j][l] = 0.0f;

#pragma unroll
    for (int v = 0; v < 2; v++) {
        int f = tid + v * 512;
        pa[v] = *reinterpret_cast<const float4*>(Aptr + (size_t)(f >> 3) * XCn + ((f & 7) << 2));
        pb[v] = *reinterpret_cast<const float4*>(Bptr + (size_t)(f >> 3) * XCn + ((f & 7) << 2));
    }

    for (int k0 = 0; k0 < XCn; k0 += 32) {
#pragma unroll
        for (int v = 0; v < 2; v++) {
            int f = tid + v * 512; int r = f >> 3, c = (f & 7) << 2;
            *reinterpret_cast<__half2*>(&As[r * 40 + c])     = __floats2half2_rn(pa[v].x, pa[v].y);
            *reinterpret_cast<__half2*>(&As[r * 40 + c + 2]) = __floats2half2_rn(pa[v].z, pa[v].w);
            *reinterpret_cast<__half2*>(&Bs[r * 40 + c])     = __floats2half2_rn(pb[v].x, pb[v].y);
            *reinterpret_cast<__half2*>(&Bs[r * 40 + c + 2]) = __floats2half2_rn(pb[v].z, pb[v].w);
        }
        __syncthreads();

        if (k0 + 32 < XCn) {
            const float* An  = Aptr + k0 + 32;
            const float* Bnp = Bptr + k0 + 32;
#pragma unroll
            for (int v = 0; v < 2; v++) {
                int f = tid + v * 512;
                pa[v] = *reinterpret_cast<const float4*>(An + (size_t)(f >> 3) * XCn + ((f & 7) << 2));
                pb[v] = *reinterpret_cast<const float4*>(Bnp + (size_t)(f >> 3) * XCn + ((f & 7) << 2));
            }
        }

#pragma unroll
        for (int ks = 0; ks < 2; ks++) {
            const int kk = ks * 16;
            uint32_t af[2][4], bf[4][2];
#pragma unroll
            for (int mt = 0; mt < 2; mt++) {
                int mb = wm * 32 + mt * 16;
                af[mt][0] = *reinterpret_cast<const uint32_t*>(&As[(mb + g) * 40 + kk + 2 * tig]);
                af[mt][1] = *reinterpret_cast<const uint32_t*>(&As[(mb + g + 8) * 40 + kk + 2 * tig]);
                af[mt][2] = *reinterpret_cast<const uint32_t*>(&As[(mb + g) * 40 + kk + 2 * tig + 8]);
                af[mt][3] = *reinterpret_cast<const uint32_t*>(&As[(mb + g + 8) * 40 + kk + 2 * tig + 8]);
            }
#pragma unroll
            for (int nt = 0; nt < 4; nt++) {
                int nb = wn * 32 + nt * 8 + g;
                bf[nt][0] = *reinterpret_cast<const uint32_t*>(&Bs[nb * 40 + kk + 2 * tig]);
                bf[nt][1] = *reinterpret_cast<const uint32_t*>(&Bs[nb * 40 + kk + 2 * tig + 8]);
            }
#pragma unroll
            for (int mt = 0; mt < 2; mt++)
#pragma unroll
                for (int nt = 0; nt < 4; nt++)
                    asm volatile(
                        "mma.sync.aligned.m16n8k16.row.col.f32.f16.f16.f32 "
                        "{%0,%1,%2,%3}, {%4,%5,%6,%7}, {%8,%9}, {%0,%1,%2,%3};"
                        : "+f"(acc[mt][nt][0]), "+f"(acc[mt][nt][1]),
                          "+f"(acc[mt][nt][2]), "+f"(acc[mt][nt][3])
                        : "r"(af[mt][0]), "r"(af[mt][1]), "r"(af[mt][2]), "r"(af[mt][3]),
                          "r"(bf[nt][0]), "r"(bf[nt][1]));
        }
        __syncthreads();
    }

    // fused LSTM epilogue in two 64-col passes through reused smem buffer
    float* gbuf = reinterpret_cast<float*>(smraw);   // [128][72]
#pragma unroll
    for (int p = 0; p < 2; p++) {
        if (p) __syncthreads();            // protect gbuf reuse
        if ((wn >> 1) == p) {
#pragma unroll
            for (int mt = 0; mt < 2; mt++) {
                int row = wm * 32 + mt * 16 + g;
#pragma unroll
                for (int nt = 0; nt < 4; nt++) {
                    int col = (wn & 1) * 32 + nt * 8 + 2 * tig;
                    gbuf[row * 72 + col]           = acc[mt][nt][0];
                    gbuf[row * 72 + col + 1]       = acc[mt][nt][1];
                    gbuf[(row + 8) * 72 + col]     = acc[mt][nt][2];
                    gbuf[(row + 8) * 72 + col + 1] = acc[mt][nt][3];
                }
            }
        }
        __syncthreads();
#pragma unroll
        for (int it = 0; it < 4; it++) {
            int idx = it * 512 + tid;          // 0..2047
            int bl = idx >> 4, nl = idx & 15;
            int b = m0 + bl;
            int ng = (n0 >> 2) + p * 16 + nl;  // output unit index
            float4 gv = *reinterpret_cast<const float4*>(&gbuf[bl * 72 + 4 * nl]);
            int tok = text[b * Sn + s];
            float4 ov = *reinterpret_cast<const float4*>(&g_ohb[(size_t)tok * 4 * Hn + 4 * ng]);
            float ig = gv.x + ov.x;
            float fg = gv.y + ov.y;
            float gg = gv.z + ov.z;
            float og = gv.w + ov.w;
            float c_old = g_c[b * Hn + ng];
            float cn = sigmoidf(fg) * c_old + sigmoidf(ig) * tanhf(gg);
            float hn = sigmoidf(og) * tanhf(cn);
            g_c[b * Hn + ng] = cn;
            g_xcat[b * XCn + Dn + ng] = hn;
            g_hs[((size_t)b * Sn + s) * Hn + ng] = hn;
        }
    }
}

// ---------------- fused attention (fp16 Hp / fp16 batch_H, fp32 elsewhere) -------
__global__ __launch_bounds__(256)
void attn_kernel(const float* __restrict__ Ws)
{
    const int b = blockIdx.x;
    __shared__ float2 ph2_s[256];
    __shared__ float2 ws2_s[256];
    __shared__ float e_s[Tn];
    __shared__ float alpha_s[Tn];

    const int tid = threadIdx.x;
    {
        float2 a = reinterpret_cast<const float2*>(g_ph + b * Hn)[tid];
#pragma unroll
        for (int z = 1; z < ZPH; z++) {
            float2 v = reinterpret_cast<const float2*>(g_ph + (size_t)z * Bn * Hn + b * Hn)[tid];
            a.x += v.x; a.y += v.y;
        }
        ph2_s[tid] = a;
        ws2_s[tid] = reinterpret_cast<const float2*>(Ws)[tid];
    }
    __syncthreads();

    const int warp = tid >> 5, lane = tid & 31;
    const __half2* hp2 = reinterpret_cast<const __half2*>(g_Hp16 + (size_t)b * Tn * Hn);

    // two score rows per warp per round (more MLP)
#pragma unroll
    for (int rr = 0; rr < 4; rr++) {
        int t0 = rr * 16 + warp * 2;
        const __half2* hA = hp2 + (size_t)t0 * 256;
        const __half2* hB = hA + 256;
        float a0 = 0.0f, a1 = 0.0f;
#pragma unroll
        for (int j = 0; j < 8; j++) {
            int h2 = lane + j * 32;
            float2 p = ph2_s[h2], w = ws2_s[h2];
            float2 vA = __half22float2(hA[h2]);
            float2 vB = __half22float2(hB[h2]);
            a0 = fmaf(tanh_fast(vA.x + p.x), w.x, a0);
            a0 = fmaf(tanh_fast(vA.y + p.y), w.y, a0);
            a1 = fmaf(tanh_fast(vB.x + p.x), w.x, a1);
            a1 = fmaf(tanh_fast(vB.y + p.y), w.y, a1);
        }
#pragma unroll
        for (int o = 16; o > 0; o >>= 1) {
            a0 += __shfl_xor_sync(0xffffffffu, a0, o);
            a1 += __shfl_xor_sync(0xffffffffu, a1, o);
        }
        if (lane == 0) { e_s[t0] = a0; e_s[t0 + 1] = a1; }
    }
    __syncthreads();

    if (warp == 0) {
        float e0 = e_s[lane], e1 = e_s[lane + 32];
        float m = fmaxf(e0, e1);
#pragma unroll
        for (int o = 16; o > 0; o >>= 1)
            m = fmaxf(m, __shfl_xor_sync(0xffffffffu, m, o));
        float x0 = expf(e0 - m), x1 = expf(e1 - m);
        float sum = x0 + x1;
#pragma unroll
        for (int o = 16; o > 0; o >>= 1)
            sum += __shfl_xor_sync(0xffffffffu, sum, o);
        float inv = 1.0f / sum;
        alpha_s[lane] = x0 * inv;
        alpha_s[lane + 32] = x1 * inv;
    }
    __syncthreads();

    const __half2* bh2 = reinterpret_cast<const __half2*>(g_bh16 + (size_t)b * Tn * Dn);
    float ax = 0.0f, ay = 0.0f;
#pragma unroll 16
    for (int t = 0; t < Tn; t++) {
        float al = alpha_s[t];
        float2 v = __half22float2(bh2[t * 256 + tid]);
        ax = fmaf(al, v.x, ax);
        ay = fmaf(al, v.y, ay);
    }
    reinterpret_cast<float2*>(g_xcat + (size_t)b * XCn)[tid] = make_float2(ax, ay);
}

// ---------------- launch ----------------
extern "C" void kernel_launch(void* const* d_in, const int* in_sizes, int n_in,
                              void* d_out, int out_size)
{
    const float* batch_H = (const float*)d_in[0];
    const int*   text    = (const int*)  d_in[1];
    const float* Wi      = (const float*)d_in[2];
    const float* Wh      = (const float*)d_in[3];
    const float* bh      = (const float*)d_in[4];
    const float* Ws      = (const float*)d_in[5];
    const float* Wih     = (const float*)d_in[6];
    const float* Whh     = (const float*)d_in[7];
    const float* bih     = (const float*)d_in[8];
    const float* bhh     = (const float*)d_in[9];
    const float* Wg      = (const float*)d_in[10];
    const float* bg      = (const float*)d_in[11];
    float* out = (float*)d_out;

    __half *Hp16, *bh16;
    float *ph, *xcat, *hs;
    cudaGetSymbolAddress((void**)&Hp16, g_Hp16);
    cudaGetSymbolAddress((void**)&bh16, g_bh16);
    cudaGetSymbolAddress((void**)&ph,   g_ph);
    cudaGetSymbolAddress((void**)&xcat, g_xcat);
    cudaGetSymbolAddress((void**)&hs,   g_hs);

    // prep
    conv_f2h<<<(Bn * Tn * Dn / 8 + 255) / 256, 256>>>(batch_H, bh16, Bn * Tn * Dn / 8);
    build_wcat_kernel<<<(4 * Hn * XCn + 255) / 256, 256>>>(Wih, Whh);
    build_ohb_kernel<<<(Cn * 4 * Hn + 255) / 256, 256>>>(Wih, bih, bhh);
    init_state_kernel<<<(Bn * Hn + 255) / 256, 256>>>();

    // Hp16 = batch_H @ Wi^T (fp16 mma, fp16 store)
    hgemm<4><<<dim3(Hn / 64, (Bn * Tn) / 128), 256>>>(
        batch_H, Dn, Wi, Dn, nullptr, Hp16, Hn, Bn * Tn, Hn, Dn);

    for (int s = 0; s < Sn; s++) {
        // ph partials: z in {0..3}, K=128 each (bias on z=0)
        hgemm<1><<<dim3(Hn / 64, Bn / 128, ZPH), 256>>>(
            xcat + Dn, XCn, Wh, Hn, bh, ph, Hn, Bn, Hn, Hn / ZPH);

        attn_kernel<<<Bn, 256>>>(Ws);

        // gates 128x128 tile, one wave, fused LSTM
        gates_kernel<<<dim3(4 * Hn / 128, Bn / 128), 512>>>(text, s);
    }

    // probs = hs @ Wg^T + bg  (fp16 mma, fp32 out, ragged N=96)
    hgemm<2><<<dim3(2, (Bn * Sn) / 128), 256>>>(
        hs, Hn, Wg, Hn, bg, out, Cn, Bn * Sn, Cn, Hn);
}